// round 5
// baseline (speedup 1.0000x reference)
#include <cuda_runtime.h>
#include <math.h>

#define NB 16
#define NA 65472
#define NC 81
#define NG 50
#define POS_TH 0.5f
#define FULL 0xffffffffu

__device__ float g_mining[NB * NA];
__device__ float g_best_iou[NB * NA];
__device__ int   g_best_idx[NB * NA];
__device__ unsigned long long g_best_anchor[NB * NG];
__device__ unsigned g_plist[NB * NA];
__device__ int    g_plist_cnt;
__device__ double g_pos_ce;
__device__ double g_loc_sum;
__device__ int    g_pos_cnt[NB];
__device__ double g_neg_sum[NB];

__device__ __forceinline__ unsigned fmap(float v) {
    unsigned u = __float_as_uint(v);
    return (u & 0x80000000u) ? ~u : (u | 0x80000000u);
}
__device__ __forceinline__ float funmap(unsigned u) {
    unsigned b = (u & 0x80000000u) ? (u & 0x7FFFFFFFu) : ~u;
    return __uint_as_float(b);
}

// ---------------------------------------------------------------- K0: init
__global__ void k0_init() {
    int t = threadIdx.x;
    if (t == 0) { g_pos_ce = 0.0; g_loc_sum = 0.0; g_plist_cnt = 0; }
    if (t < NB) { g_pos_cnt[t] = 0; g_neg_sum[t] = 0.0; }
    // iou=0, anchor=0 (~a = 0xFFFFFFFF) -> matches argmax default when all ious are 0
    for (int i = t; i < NB * NG; i += blockDim.x) g_best_anchor[i] = 0xFFFFFFFFull;
}

// ------------------------------------------------- K1: logsumexp -> mining
__global__ void k1_lse(const float* __restrict__ conf) {
    int warp = threadIdx.x >> 5;
    int lane = threadIdx.x & 31;
    int a = blockIdx.x * (blockDim.x >> 5) + warp;
    int b = blockIdx.y;
    const float* p = conf + ((size_t)b * NA + a) * NC;
    float x0 = p[lane];
    float x1 = p[32 + lane];
    float s = __expf(x0) + __expf(x1);
    if (lane < NC - 64) s += __expf(p[64 + lane]);
    #pragma unroll
    for (int off = 16; off; off >>= 1) s += __shfl_xor_sync(FULL, s, off);
    if (lane == 0) g_mining[(size_t)b * NA + a] = __logf(s) - x0;  // lse - conf[...,0]
}

// -------- K2: fused per-anchor best + per-g argmax + positive-list append
__global__ void k2_match(const float* __restrict__ gts, const int* __restrict__ counts,
                         const float* __restrict__ anchors) {
    __shared__ float4 sbox[NG];
    __shared__ float  sarea[NG];
    int b = blockIdx.y;
    int tid = threadIdx.x;
    int a = blockIdx.x * blockDim.x + tid;
    int lane = tid & 31;
    if (tid < NG) {
        const float* gp = gts + ((size_t)b * NG + tid) * 5;
        float4 bx = make_float4(gp[0], gp[1], gp[2], gp[3]);
        sbox[tid] = bx;
        sarea[tid] = (bx.z - bx.x) * (bx.w - bx.y);
    }
    __syncthreads();
    int count = counts[b];
    float4 v = make_float4(0.f, 0.f, 0.f, 0.f);
    if (a < NA) v = reinterpret_cast<const float4*>(anchors)[a];
    float areaA = (v.z - v.x) * (v.w - v.y);
    float bi = -1.f;
    int bidx = 0;
    for (int g = 0; g < count; ++g) {
        float4 bx = sbox[g];
        float wx = fminf(v.z, bx.z) - fmaxf(v.x, bx.x);
        float wy = fminf(v.w, bx.w) - fmaxf(v.y, bx.y);
        wx = fmaxf(wx, 0.f); wy = fmaxf(wy, 0.f);
        float inter = wx * wy;
        float iou = __fdividef(inter, areaA + sarea[g] - inter + 1e-10f);
        if (a >= NA) iou = 0.f;
        if (iou > bi) { bi = iou; bidx = g; }          // first max kept (strict >)
        // per-g warp argmax; ties -> smallest lane = smallest anchor index
        unsigned any = __ballot_sync(FULL, iou > 0.f);
        if (any) {
            float m = iou;
            #pragma unroll
            for (int off = 16; off; off >>= 1) m = fmaxf(m, __shfl_xor_sync(FULL, m, off));
            unsigned ball = __ballot_sync(FULL, iou == m);
            if (lane == (__ffs(ball) - 1)) {
                unsigned long long pk =
                    ((unsigned long long)__float_as_uint(iou) << 32) |
                    (unsigned)(~(unsigned)a);
                atomicMax(&g_best_anchor[b * NG + g], pk);
            }
        }
    }
    bool reg_pos = (a < NA) && (bi >= POS_TH);
    if (a < NA) {
        g_best_iou[(size_t)b * NA + a] = bi;
        g_best_idx[(size_t)b * NA + a] = bidx;
    }
    // warp-aggregated append of regular positives
    unsigned ball = __ballot_sync(FULL, reg_pos);
    if (ball) {
        int leader = __ffs(ball) - 1;
        int base = 0;
        if (lane == leader) base = atomicAdd(&g_plist_cnt, __popc(ball));
        base = __shfl_sync(FULL, base, leader);
        if (reg_pos) {
            int off = __popc(ball & ((1u << lane) - 1u));
            g_plist[base + off] = ((unsigned)b << 17) | (unsigned)a;
        }
    }
}

// ------ K3: forced-positive scatter (last-wins dedup) + append new positives
__global__ void k3_scatter(const int* __restrict__ counts) {
    __shared__ int s_anch[NB * 64];
    __shared__ int s_cnt[NB];
    int tid = threadIdx.x;
    int b = tid >> 6;       // 64 threads per batch (NG=50 < 64)
    int g = tid & 63;
    if (g == 0 && b < NB) s_cnt[b] = counts[b];
    __syncthreads();
    int cnt = (b < NB) ? s_cnt[b] : 0;
    bool act = (b < NB) && (g < cnt);
    int a = -1;
    if (act) {
        unsigned long long pk = g_best_anchor[b * NG + g];
        a = (int)(~(unsigned)(pk & 0xFFFFFFFFu));
    }
    s_anch[tid] = a;
    __syncthreads();
    if (act) {
        bool skip = false;
        for (int g2 = g + 1; g2 < cnt; ++g2)       // last write wins
            if (s_anch[(b << 6) + g2] == a) { skip = true; break; }
        if (!skip) {
            size_t ia = (size_t)b * NA + a;
            float old = g_best_iou[ia];
            g_best_idx[ia] = g;
            g_best_iou[ia] = 2.0f;
            if (old < POS_TH) {   // newly-forced positive -> append
                int idx = atomicAdd(&g_plist_cnt, 1);
                g_plist[idx] = ((unsigned)b << 17) | (unsigned)a;
            }
        }
    }
}

// ------- K4: compact positives: CE, SmoothL1, counts, mask mining = -inf
__global__ void k4_pos(const float* __restrict__ conf, const float* __restrict__ pred,
                       const float* __restrict__ gts, const float* __restrict__ anchors) {
    int n = g_plist_cnt;
    float ce_acc = 0.f, loc_acc = 0.f;
    bool any = false;
    for (int i = blockIdx.x * blockDim.x + threadIdx.x; i < n; i += gridDim.x * blockDim.x) {
        unsigned e = g_plist[i];
        int b = e >> 17;
        int a = e & 0x1FFFF;
        size_t ia = (size_t)b * NA + a;
        int g = g_best_idx[ia];
        const float* gp = gts + ((size_t)b * NG + g) * 5;
        int label = (int)gp[4];
        const float* cp = conf + ia * NC;
        float m = g_mining[ia];
        ce_acc += m + cp[0] - cp[label];              // lse - conf[label]
        g_mining[ia] = -INFINITY;
        float4 av = reinterpret_cast<const float4*>(anchors)[a];
        float acx = (av.x + av.z) * 0.5f, acy = (av.y + av.w) * 0.5f;
        float aw = av.z - av.x, ah = av.w - av.y;
        float mcx = (gp[0] + gp[2]) * 0.5f, mcy = (gp[1] + gp[3]) * 0.5f;
        float mw = gp[2] - gp[0], mh = gp[3] - gp[1];
        float t0 = (mcx - acx) / (aw * 0.1f);
        float t1 = (mcy - acy) / (ah * 0.1f);
        float t2 = logf(mw / aw + 1e-10f) / 0.2f;
        float t3 = logf(mh / ah + 1e-10f) / 0.2f;
        float4 pv = reinterpret_cast<const float4*>(pred)[ia];
        const float BETA = (float)(1.0 / 9.0);
        float d;
        d = fabsf(pv.x - t0); loc_acc += (d < BETA) ? 0.5f * d * d / BETA : d - 0.5f * BETA;
        d = fabsf(pv.y - t1); loc_acc += (d < BETA) ? 0.5f * d * d / BETA : d - 0.5f * BETA;
        d = fabsf(pv.z - t2); loc_acc += (d < BETA) ? 0.5f * d * d / BETA : d - 0.5f * BETA;
        d = fabsf(pv.w - t3); loc_acc += (d < BETA) ? 0.5f * d * d / BETA : d - 0.5f * BETA;
        atomicAdd(&g_pos_cnt[b], 1);
        any = true;
    }
    unsigned ball = __ballot_sync(FULL, any);
    #pragma unroll
    for (int off = 16; off; off >>= 1) {
        ce_acc  += __shfl_xor_sync(FULL, ce_acc, off);
        loc_acc += __shfl_xor_sync(FULL, loc_acc, off);
    }
    if ((threadIdx.x & 31) == 0 && ball) {
        atomicAdd(&g_pos_ce, (double)ce_acc);
        atomicAdd(&g_loc_sum, (double)loc_acc);
    }
}

// -- K5: per-batch radix-select of K-th largest mining + top-K sum (fused)
__global__ void k5_select_sum() {
    __shared__ int hist[2048];
    __shared__ unsigned s_pref;
    __shared__ int s_rem, s_selbin, s_above;
    __shared__ double sred[32];
    int b = blockIdx.x;
    int tid = threadIdx.x;
    int lane = tid & 31;
    const float* base = g_mining + (size_t)b * NA;
    int K = 3 * g_pos_cnt[b];
    if (K > NA) K = NA;
    if (K <= 0) { if (tid == 0) g_neg_sum[b] = 0.0; return; }
    if (tid == 0) { s_rem = K; s_pref = 0u; }
    __syncthreads();
    for (int pass = 0; pass < 3; ++pass) {
        for (int i = tid; i < 2048; i += blockDim.x) hist[i] = 0;
        __syncthreads();
        unsigned pref = s_pref;
        int nb = (pass == 2) ? 1024 : 2048;
        for (int i = tid; i < NA; i += blockDim.x) {
            unsigned u = fmap(base[i]);
            unsigned bin; bool ok;
            if (pass == 0)      { ok = true;                 bin = u >> 21; }
            else if (pass == 1) { ok = ((u >> 21) == pref);  bin = (u >> 10) & 0x7FFu; }
            else                { ok = ((u >> 10) == pref);  bin = u & 0x3FFu; }
            // warp-aggregate same-bin increments (concentrated distribution!)
            unsigned mm = __match_any_sync(FULL, ok ? bin : 0xFFFFFFFFu);
            if (ok && lane == (__ffs(mm) - 1)) atomicAdd(&hist[bin], __popc(mm));
        }
        __syncthreads();
        if (tid < 32) {
            int cs = nb >> 5;
            int s = 0;
            for (int k = 0; k < cs; k++) s += hist[lane * cs + k];
            int inc = s;
            #pragma unroll
            for (int off = 1; off < 32; off <<= 1) {
                int t = __shfl_down_sync(FULL, inc, off);
                if (lane + off < 32) inc += t;
            }
            int exc = inc - s;             // count in chunks strictly above
            int remv = s_rem;
            bool hit = (exc < remv) && (inc >= remv);
            unsigned bal = __ballot_sync(FULL, hit);
            int src = __ffs(bal) - 1;
            if (lane == src) {
                int cum = exc, selbin = lane * cs;
                for (int bb = lane * cs + cs - 1; bb >= lane * cs; --bb) {
                    int h = hist[bb];
                    if (cum + h >= remv) { selbin = bb; break; }
                    cum += h;
                }
                s_selbin = selbin;
                s_above = cum;
            }
        }
        __syncthreads();
        if (tid == 0) {
            s_rem -= s_above;
            s_pref = (pass == 0) ? (unsigned)s_selbin
                                 : ((s_pref << ((pass == 2) ? 10 : 11)) | (unsigned)s_selbin);
        }
        __syncthreads();
    }
    // 4th pass: sum all values strictly above threshold, plus tie term
    unsigned ut = s_pref;
    double s = 0.0;
    for (int i = tid; i < NA; i += blockDim.x) {
        float v = base[i];
        if (fmap(v) > ut) s += (double)v;
    }
    #pragma unroll
    for (int off = 16; off; off >>= 1) s += __shfl_xor_sync(FULL, s, off);
    if (lane == 0) sred[tid >> 5] = s;
    __syncthreads();
    if (tid < 32) {
        double v = (tid < (int)(blockDim.x >> 5)) ? sred[tid] : 0.0;
        #pragma unroll
        for (int off = 16; off; off >>= 1) v += __shfl_xor_sync(FULL, v, off);
        if (tid == 0) {
            float tv = funmap(ut);
            if (isfinite(tv)) v += (double)s_rem * (double)tv;  // ties at threshold
            g_neg_sum[b] = v;
        }
    }
}

// ------------------------------------------------------------ K7: finalize
__global__ void k7_final(float* __restrict__ out) {
    if (threadIdx.x == 0) {
        int np = 0; double ns = 0.0;
        for (int b = 0; b < NB; b++) { np += g_pos_cnt[b]; ns += g_neg_sum[b]; }
        float npf = fmaxf(1.f, (float)np);
        double denom = (double)npf * 4.0;
        out[0] = (float)(g_loc_sum / denom);          // localisation_loss
        out[1] = (float)((g_pos_ce + ns) / denom);    // classification_loss
    }
}

extern "C" void kernel_launch(void* const* d_in, const int* in_sizes, int n_in,
                              void* d_out, int out_size) {
    const float* conf    = (const float*)d_in[0];
    const float* pred    = (const float*)d_in[1];
    const float* gts     = (const float*)d_in[2];
    const int*   counts  = (const int*)d_in[3];
    const float* anchors = (const float*)d_in[4];
    float* out = (float*)d_out;

    k0_init<<<1, 256>>>();
    k1_lse<<<dim3(NA / 8, NB), 256>>>(conf);
    k2_match<<<dim3((NA + 255) / 256, NB), 256>>>(gts, counts, anchors);
    k3_scatter<<<1, 1024>>>(counts);
    k4_pos<<<64, 256>>>(conf, pred, gts, anchors);
    k5_select_sum<<<NB, 1024>>>();
    k7_final<<<1, 32>>>(out);
}

// round 7
// speedup vs baseline: 1.2021x; 1.2021x over previous
#include <cuda_runtime.h>
#include <math.h>

#define NB 16
#define NA 65472
#define NC 81
#define NG 50
#define POS_TH 0.5f
#define FULL 0xffffffffu
#define WPB 2048   // warps per batch in k2a (256 blocks x 8 warps)

__device__ float g_mining[NB * NA];
__device__ float g_best_iou[NB * NA];
__device__ int   g_best_idx[NB * NA];
__device__ unsigned long long g_part[NB * NG * WPB];
__device__ unsigned g_plist[NB * NA];
__device__ int    g_plist_cnt;
__device__ double g_pos_ce;
__device__ double g_loc_sum;
__device__ int    g_pos_cnt[NB];
__device__ double g_neg_sum[NB];

__device__ __forceinline__ unsigned fmap(float v) {
    unsigned u = __float_as_uint(v);
    return (u & 0x80000000u) ? ~u : (u | 0x80000000u);
}
__device__ __forceinline__ float funmap(unsigned u) {
    unsigned b = (u & 0x80000000u) ? (u & 0x7FFFFFFFu) : ~u;
    return __uint_as_float(b);
}

// ---------------------- K1: logsumexp -> mining  (+ scalar init in block 0)
__global__ void k1_lse(const float* __restrict__ conf) {
    if (blockIdx.x == 0 && blockIdx.y == 0 && threadIdx.x < 32) {
        int t = threadIdx.x;
        if (t == 0) { g_pos_ce = 0.0; g_loc_sum = 0.0; g_plist_cnt = 0; }
        if (t < NB) { g_pos_cnt[t] = 0; g_neg_sum[t] = 0.0; }
    }
    int warp = threadIdx.x >> 5;
    int lane = threadIdx.x & 31;
    int a = blockIdx.x * (blockDim.x >> 5) + warp;
    int b = blockIdx.y;
    const float* p = conf + ((size_t)b * NA + a) * NC;
    float x0 = p[lane];
    float x1 = p[32 + lane];
    float s = __expf(x0) + __expf(x1);
    if (lane < NC - 64) s += __expf(p[64 + lane]);
    #pragma unroll
    for (int off = 16; off; off >>= 1) s += __shfl_xor_sync(FULL, s, off);
    if (lane == 0) g_mining[(size_t)b * NA + a] = __logf(s) - x0;  // lse - conf[...,0]
}

// --- K2a: per-anchor best + per-(warp,g) argmax partials + positive append
__global__ void k2a_match(const float* __restrict__ gts, const int* __restrict__ counts,
                          const float* __restrict__ anchors) {
    __shared__ float4 sbox[NG];
    __shared__ float  sarea[NG];
    int b = blockIdx.y;
    int tid = threadIdx.x;
    int a = blockIdx.x * blockDim.x + tid;
    int lane = tid & 31;
    int wgl = blockIdx.x * (blockDim.x >> 5) + (tid >> 5);   // warp id within batch
    if (tid < NG) {
        const float* gp = gts + ((size_t)b * NG + tid) * 5;
        float4 bx = make_float4(gp[0], gp[1], gp[2], gp[3]);
        sbox[tid] = bx;
        sarea[tid] = (bx.z - bx.x) * (bx.w - bx.y);
    }
    __syncthreads();
    int count = counts[b];
    float4 v = make_float4(0.f, 0.f, 0.f, 0.f);
    if (a < NA) v = reinterpret_cast<const float4*>(anchors)[a];
    float areaA = (v.z - v.x) * (v.w - v.y);
    float bi = -1.f;
    int bidx = 0;
    for (int g = 0; g < count; ++g) {
        float4 bx = sbox[g];
        float wx = fminf(v.z, bx.z) - fmaxf(v.x, bx.x);
        float wy = fminf(v.w, bx.w) - fmaxf(v.y, bx.y);
        wx = fmaxf(wx, 0.f); wy = fmaxf(wy, 0.f);
        float inter = wx * wy;
        float iou = __fdividef(inter, areaA + sarea[g] - inter + 1e-10f);
        if (a >= NA) iou = 0.f;
        if (iou > bi) { bi = iou; bidx = g; }          // first max kept (strict >)
        // per-(warp,g) argmax partial; ties -> smallest lane = smallest anchor
        float m = iou;
        #pragma unroll
        for (int off = 16; off; off >>= 1) m = fmaxf(m, __shfl_xor_sync(FULL, m, off));
        unsigned ball = __ballot_sync(FULL, iou == m);
        if (lane == (__ffs(ball) - 1)) {
            g_part[((size_t)b * NG + g) * WPB + wgl] =
                ((unsigned long long)__float_as_uint(m) << 32) | (unsigned)(~(unsigned)a);
        }
    }
    bool reg_pos = (a < NA) && (bi >= POS_TH);
    if (a < NA) {
        g_best_iou[(size_t)b * NA + a] = bi;
        g_best_idx[(size_t)b * NA + a] = bidx;
    }
    // warp-aggregated append of regular positives
    unsigned ball = __ballot_sync(FULL, reg_pos);
    if (ball) {
        int leader = __ffs(ball) - 1;
        int base = 0;
        if (lane == leader) base = atomicAdd(&g_plist_cnt, __popc(ball));
        base = __shfl_sync(FULL, base, leader);
        if (reg_pos) {
            int off = __popc(ball & ((1u << lane) - 1u));
            g_plist[base + off] = ((unsigned)b << 17) | (unsigned)a;
        }
    }
}

// --- K2b3: reduce per-warp partials -> best anchor per g; then dedup+scatter
// one block per batch, 512 threads
__global__ void k2b3_reduce_scatter(const int* __restrict__ counts) {
    __shared__ unsigned long long swr[16];
    __shared__ int s_anch[NG];
    int b = blockIdx.x;
    int tid = threadIdx.x;
    int lane = tid & 31;
    int wid = tid >> 5;
    int count = counts[b];
    for (int g = 0; g < count; ++g) {
        const unsigned long long* pp = g_part + ((size_t)b * NG + g) * WPB;
        unsigned long long best = 0ull;
        #pragma unroll
        for (int k = 0; k < WPB / 512; ++k) {
            unsigned long long v = pp[tid + k * 512];
            if (v > best) best = v;
        }
        #pragma unroll
        for (int off = 16; off; off >>= 1) {
            unsigned long long o = __shfl_xor_sync(FULL, best, off);
            if (o > best) best = o;
        }
        if (lane == 0) swr[wid] = best;
        __syncthreads();
        if (tid < 32) {
            unsigned long long v = (lane < 16) ? swr[lane] : 0ull;
            #pragma unroll
            for (int off = 8; off; off >>= 1) {
                unsigned long long o = __shfl_xor_sync(FULL, v, off);
                if (o > v) v = o;
            }
            if (lane == 0) s_anch[g] = (int)(~(unsigned)(v & 0xFFFFFFFFu));
        }
        __syncthreads();
    }
    // dedup (last write wins) + scatter + append newly-forced positives
    if (tid < count) {
        int g = tid;
        int a = s_anch[g];
        bool skip = false;
        for (int g2 = g + 1; g2 < count; ++g2)
            if (s_anch[g2] == a) { skip = true; break; }
        if (!skip) {
            size_t ia = (size_t)b * NA + a;
            float old = g_best_iou[ia];
            g_best_idx[ia] = g;
            g_best_iou[ia] = 2.0f;
            if (old < POS_TH) {
                int idx = atomicAdd(&g_plist_cnt, 1);
                g_plist[idx] = ((unsigned)b << 17) | (unsigned)a;
            }
        }
    }
}

// ------- K4: compact positives: CE, SmoothL1, counts, mask mining = -inf
__global__ void k4_pos(const float* __restrict__ conf, const float* __restrict__ pred,
                       const float* __restrict__ gts, const float* __restrict__ anchors) {
    int n = g_plist_cnt;
    int lane = threadIdx.x & 31;
    float ce_acc = 0.f, loc_acc = 0.f;
    bool any = false;
    for (int i = blockIdx.x * blockDim.x + threadIdx.x; i < n; i += gridDim.x * blockDim.x) {
        unsigned e = g_plist[i];
        int b = e >> 17;
        int a = e & 0x1FFFF;
        size_t ia = (size_t)b * NA + a;
        int g = g_best_idx[ia];
        const float* gp = gts + ((size_t)b * NG + g) * 5;
        int label = (int)gp[4];
        const float* cp = conf + ia * NC;
        float m = g_mining[ia];
        ce_acc += m + cp[0] - cp[label];              // lse - conf[label]
        g_mining[ia] = -INFINITY;
        float4 av = reinterpret_cast<const float4*>(anchors)[a];
        float acx = (av.x + av.z) * 0.5f, acy = (av.y + av.w) * 0.5f;
        float aw = av.z - av.x, ah = av.w - av.y;
        float mcx = (gp[0] + gp[2]) * 0.5f, mcy = (gp[1] + gp[3]) * 0.5f;
        float mw = gp[2] - gp[0], mh = gp[3] - gp[1];
        float t0 = (mcx - acx) / (aw * 0.1f);
        float t1 = (mcy - acy) / (ah * 0.1f);
        float t2 = logf(mw / aw + 1e-10f) / 0.2f;
        float t3 = logf(mh / ah + 1e-10f) / 0.2f;
        float4 pv = reinterpret_cast<const float4*>(pred)[ia];
        const float BETA = (float)(1.0 / 9.0);
        float d;
        d = fabsf(pv.x - t0); loc_acc += (d < BETA) ? 0.5f * d * d / BETA : d - 0.5f * BETA;
        d = fabsf(pv.y - t1); loc_acc += (d < BETA) ? 0.5f * d * d / BETA : d - 0.5f * BETA;
        d = fabsf(pv.z - t2); loc_acc += (d < BETA) ? 0.5f * d * d / BETA : d - 0.5f * BETA;
        d = fabsf(pv.w - t3); loc_acc += (d < BETA) ? 0.5f * d * d / BETA : d - 0.5f * BETA;
        // warp-aggregated per-batch positive count
        unsigned mm = __match_any_sync(__activemask(), b);
        if (lane == (__ffs(mm) - 1)) atomicAdd(&g_pos_cnt[b], __popc(mm));
        any = true;
    }
    unsigned ball = __ballot_sync(FULL, any);
    #pragma unroll
    for (int off = 16; off; off >>= 1) {
        ce_acc  += __shfl_xor_sync(FULL, ce_acc, off);
        loc_acc += __shfl_xor_sync(FULL, loc_acc, off);
    }
    if (lane == 0 && ball) {
        atomicAdd(&g_pos_ce, (double)ce_acc);
        atomicAdd(&g_loc_sum, (double)loc_acc);
    }
}

// -- K5: per-batch radix-select of K-th largest mining + top-K sum (fused)
__global__ void k5_select_sum() {
    __shared__ int hist[2048];
    __shared__ unsigned s_pref;
    __shared__ int s_rem, s_selbin, s_above;
    __shared__ double sred[32];
    int b = blockIdx.x;
    int tid = threadIdx.x;
    int lane = tid & 31;
    const float* base = g_mining + (size_t)b * NA;
    int K = 3 * g_pos_cnt[b];
    if (K > NA) K = NA;
    if (K <= 0) { if (tid == 0) g_neg_sum[b] = 0.0; return; }
    if (tid == 0) { s_rem = K; s_pref = 0u; }
    __syncthreads();
    for (int pass = 0; pass < 3; ++pass) {
        for (int i = tid; i < 2048; i += blockDim.x) hist[i] = 0;
        __syncthreads();
        unsigned pref = s_pref;
        int nb = (pass == 2) ? 1024 : 2048;
        for (int i = tid; i < NA; i += blockDim.x) {
            unsigned u = fmap(base[i]);
            unsigned bin; bool ok;
            if (pass == 0)      { ok = true;                 bin = u >> 21; }
            else if (pass == 1) { ok = ((u >> 21) == pref);  bin = (u >> 10) & 0x7FFu; }
            else                { ok = ((u >> 10) == pref);  bin = u & 0x3FFu; }
            // warp-aggregate same-bin increments (concentrated distribution)
            unsigned mm = __match_any_sync(FULL, ok ? bin : 0xFFFFFFFFu);
            if (ok && lane == (__ffs(mm) - 1)) atomicAdd(&hist[bin], __popc(mm));
        }
        __syncthreads();
        if (tid < 32) {
            int cs = nb >> 5;
            int s = 0;
            for (int k = 0; k < cs; k++) s += hist[lane * cs + k];
            int inc = s;
            #pragma unroll
            for (int off = 1; off < 32; off <<= 1) {
                int t = __shfl_down_sync(FULL, inc, off);
                if (lane + off < 32) inc += t;
            }
            int exc = inc - s;             // count in chunks strictly above
            int remv = s_rem;
            bool hit = (exc < remv) && (inc >= remv);
            unsigned bal = __ballot_sync(FULL, hit);
            int src = __ffs(bal) - 1;
            if (lane == src) {
                int cum = exc, selbin = lane * cs;
                for (int bb = lane * cs + cs - 1; bb >= lane * cs; --bb) {
                    int h = hist[bb];
                    if (cum + h >= remv) { selbin = bb; break; }
                    cum += h;
                }
                s_selbin = selbin;
                s_above = cum;
            }
        }
        __syncthreads();
        if (tid == 0) {
            s_rem -= s_above;
            s_pref = (pass == 0) ? (unsigned)s_selbin
                                 : ((s_pref << ((pass == 2) ? 10 : 11)) | (unsigned)s_selbin);
        }
        __syncthreads();
    }
    // 4th pass: sum all values strictly above threshold, plus tie term
    unsigned ut = s_pref;
    double s = 0.0;
    for (int i = tid; i < NA; i += blockDim.x) {
        float v = base[i];
        if (fmap(v) > ut) s += (double)v;
    }
    #pragma unroll
    for (int off = 16; off; off >>= 1) s += __shfl_xor_sync(FULL, s, off);
    if (lane == 0) sred[tid >> 5] = s;
    __syncthreads();
    if (tid < 32) {
        double v = (tid < (int)(blockDim.x >> 5)) ? sred[tid] : 0.0;
        #pragma unroll
        for (int off = 16; off; off >>= 1) v += __shfl_xor_sync(FULL, v, off);
        if (tid == 0) {
            float tv = funmap(ut);
            if (isfinite(tv)) v += (double)s_rem * (double)tv;  // ties at threshold
            g_neg_sum[b] = v;
        }
    }
}

// ------------------------------------------------------------ K7: finalize
__global__ void k7_final(float* __restrict__ out) {
    if (threadIdx.x == 0) {
        int np = 0; double ns = 0.0;
        for (int b = 0; b < NB; b++) { np += g_pos_cnt[b]; ns += g_neg_sum[b]; }
        float npf = fmaxf(1.f, (float)np);
        double denom = (double)npf * 4.0;
        out[0] = (float)(g_loc_sum / denom);          // localisation_loss
        out[1] = (float)((g_pos_ce + ns) / denom);    // classification_loss
    }
}

extern "C" void kernel_launch(void* const* d_in, const int* in_sizes, int n_in,
                              void* d_out, int out_size) {
    const float* conf    = (const float*)d_in[0];
    const float* pred    = (const float*)d_in[1];
    const float* gts     = (const float*)d_in[2];
    const int*   counts  = (const int*)d_in[3];
    const float* anchors = (const float*)d_in[4];
    float* out = (float*)d_out;

    k1_lse<<<dim3(NA / 8, NB), 256>>>(conf);
    k2a_match<<<dim3((NA + 255) / 256, NB), 256>>>(gts, counts, anchors);
    k2b3_reduce_scatter<<<NB, 512>>>(counts);
    k4_pos<<<64, 256>>>(conf, pred, gts, anchors);
    k5_select_sum<<<NB, 1024>>>();
    k7_final<<<1, 32>>>(out);
}

// round 11
// speedup vs baseline: 1.4400x; 1.1979x over previous
#include <cuda_runtime.h>
#include <math.h>

#define NB 16
#define NA 65472
#define NC 81
#define NG 50
#define POS_TH 0.5f
#define FULL 0xffffffffu
#define WPB 2048   // warps per batch in k2a (256 blocks x 8 warps)

__device__ float g_mining[NB * NA];
__device__ float g_best_iou[NB * NA];
__device__ int   g_best_idx[NB * NA];
__device__ unsigned long long g_part[NB * NG * WPB];
__device__ unsigned g_plist[NB * NA];
__device__ int    g_plist_cnt;
__device__ double g_pos_ce;
__device__ double g_loc_sum;
__device__ int    g_pos_cnt[NB];
__device__ double g_neg_sum[NB];
__device__ int    g_done;

__device__ __forceinline__ unsigned fmap(float v) {
    unsigned u = __float_as_uint(v);
    return (u & 0x80000000u) ? ~u : (u | 0x80000000u);
}
__device__ __forceinline__ float funmap(unsigned u) {
    unsigned b = (u & 0x80000000u) ? (u & 0x7FFFFFFFu) : ~u;
    return __uint_as_float(b);
}

// ---------------------- K1: logsumexp -> mining  (+ scalar init in block 0)
__global__ void k1_lse(const float* __restrict__ conf) {
    if (blockIdx.x == 0 && blockIdx.y == 0 && threadIdx.x < 32) {
        int t = threadIdx.x;
        if (t == 0) { g_pos_ce = 0.0; g_loc_sum = 0.0; g_plist_cnt = 0; g_done = 0; }
        if (t < NB) { g_pos_cnt[t] = 0; g_neg_sum[t] = 0.0; }
    }
    int warp = threadIdx.x >> 5;
    int lane = threadIdx.x & 31;
    int a = blockIdx.x * (blockDim.x >> 5) + warp;
    int b = blockIdx.y;
    const float* p = conf + ((size_t)b * NA + a) * NC;
    float x0 = p[lane];
    float x1 = p[32 + lane];
    float s = __expf(x0) + __expf(x1);
    if (lane < NC - 64) s += __expf(p[64 + lane]);
    #pragma unroll
    for (int off = 16; off; off >>= 1) s += __shfl_xor_sync(FULL, s, off);
    if (lane == 0) g_mining[(size_t)b * NA + a] = __logf(s) - x0;  // lse - conf[...,0]
}

// --- K2a: per-anchor best + per-(warp,g) argmax partials + positive append
__global__ void k2a_match(const float* __restrict__ gts, const int* __restrict__ counts,
                          const float* __restrict__ anchors) {
    __shared__ float4 sbox[NG];
    __shared__ float  sarea[NG];
    int b = blockIdx.y;
    int tid = threadIdx.x;
    int a = blockIdx.x * blockDim.x + tid;
    int lane = tid & 31;
    int wgl = blockIdx.x * (blockDim.x >> 5) + (tid >> 5);   // warp id within batch
    if (tid < NG) {
        const float* gp = gts + ((size_t)b * NG + tid) * 5;
        float4 bx = make_float4(gp[0], gp[1], gp[2], gp[3]);
        sbox[tid] = bx;
        sarea[tid] = (bx.z - bx.x) * (bx.w - bx.y);
    }
    __syncthreads();
    int count = counts[b];
    float4 v = make_float4(0.f, 0.f, 0.f, 0.f);
    if (a < NA) v = reinterpret_cast<const float4*>(anchors)[a];
    float areaA = (v.z - v.x) * (v.w - v.y);
    float bi = -1.f;
    int bidx = 0;
    for (int g = 0; g < count; ++g) {
        float4 bx = sbox[g];
        float wx = fminf(v.z, bx.z) - fmaxf(v.x, bx.x);
        float wy = fminf(v.w, bx.w) - fmaxf(v.y, bx.y);
        wx = fmaxf(wx, 0.f); wy = fmaxf(wy, 0.f);
        float inter = wx * wy;
        float iou = __fdividef(inter, areaA + sarea[g] - inter + 1e-10f);
        if (a >= NA) iou = 0.f;
        if (iou > bi) { bi = iou; bidx = g; }          // first max kept (strict >)
        // per-(warp,g) argmax partial via hardware REDUX (iou >= 0 so uint order = float order)
        unsigned iu = __float_as_uint(iou);
        unsigned mu = __reduce_max_sync(FULL, iu);
        unsigned ball = __ballot_sync(FULL, iu == mu);
        if (lane == (__ffs(ball) - 1)) {               // lowest lane = smallest anchor
            g_part[((size_t)b * NG + g) * WPB + wgl] =
                ((unsigned long long)mu << 32) | (unsigned)(~(unsigned)a);
        }
    }
    bool reg_pos = (a < NA) && (bi >= POS_TH);
    if (a < NA) {
        g_best_iou[(size_t)b * NA + a] = bi;
        g_best_idx[(size_t)b * NA + a] = bidx;
    }
    // warp-aggregated append of regular positives
    unsigned ball = __ballot_sync(FULL, reg_pos);
    if (ball) {
        int leader = __ffs(ball) - 1;
        int base = 0;
        if (lane == leader) base = atomicAdd(&g_plist_cnt, __popc(ball));
        base = __shfl_sync(FULL, base, leader);
        if (reg_pos) {
            int off = __popc(ball & ((1u << lane) - 1u));
            g_plist[base + off] = ((unsigned)b << 17) | (unsigned)a;
        }
    }
}

// --- K2b3: reduce per-warp partials -> best anchor per g; then dedup+scatter
__global__ void k2b3_reduce_scatter(const int* __restrict__ counts) {
    __shared__ unsigned long long swr[16];
    __shared__ int s_anch[NG];
    int b = blockIdx.x;
    int tid = threadIdx.x;
    int lane = tid & 31;
    int wid = tid >> 5;
    int count = counts[b];
    for (int g = 0; g < count; ++g) {
        const unsigned long long* pp = g_part + ((size_t)b * NG + g) * WPB;
        unsigned long long best = 0ull;
        #pragma unroll
        for (int k = 0; k < WPB / 512; ++k) {
            unsigned long long v = pp[tid + k * 512];
            if (v > best) best = v;
        }
        #pragma unroll
        for (int off = 16; off; off >>= 1) {
            unsigned long long o = __shfl_xor_sync(FULL, best, off);
            if (o > best) best = o;
        }
        if (lane == 0) swr[wid] = best;
        __syncthreads();
        if (tid < 32) {
            unsigned long long v = (lane < 16) ? swr[lane] : 0ull;
            #pragma unroll
            for (int off = 8; off; off >>= 1) {
                unsigned long long o = __shfl_xor_sync(FULL, v, off);
                if (o > v) v = o;
            }
            if (lane == 0) s_anch[g] = (int)(~(unsigned)(v & 0xFFFFFFFFu));
        }
        __syncthreads();
    }
    // dedup (last write wins) + scatter + append newly-forced positives
    if (tid < count) {
        int g = tid;
        int a = s_anch[g];
        bool skip = false;
        for (int g2 = g + 1; g2 < count; ++g2)
            if (s_anch[g2] == a) { skip = true; break; }
        if (!skip) {
            size_t ia = (size_t)b * NA + a;
            float old = g_best_iou[ia];
            g_best_idx[ia] = g;
            g_best_iou[ia] = 2.0f;
            if (old < POS_TH) {
                int idx = atomicAdd(&g_plist_cnt, 1);
                g_plist[idx] = ((unsigned)b << 17) | (unsigned)a;
            }
        }
    }
}

// ------- K4: compact positives: CE, SmoothL1, counts, mask mining = -inf
__global__ void k4_pos(const float* __restrict__ conf, const float* __restrict__ pred,
                       const float* __restrict__ gts, const float* __restrict__ anchors) {
    int n = g_plist_cnt;
    int lane = threadIdx.x & 31;
    float ce_acc = 0.f, loc_acc = 0.f;
    bool any = false;
    for (int i = blockIdx.x * blockDim.x + threadIdx.x; i < n; i += gridDim.x * blockDim.x) {
        unsigned e = g_plist[i];
        int b = e >> 17;
        int a = e & 0x1FFFF;
        size_t ia = (size_t)b * NA + a;
        int g = g_best_idx[ia];
        const float* gp = gts + ((size_t)b * NG + g) * 5;
        int label = (int)gp[4];
        const float* cp = conf + ia * NC;
        float m = g_mining[ia];
        ce_acc += m + cp[0] - cp[label];              // lse - conf[label]
        g_mining[ia] = -INFINITY;
        float4 av = reinterpret_cast<const float4*>(anchors)[a];
        float acx = (av.x + av.z) * 0.5f, acy = (av.y + av.w) * 0.5f;
        float aw = av.z - av.x, ah = av.w - av.y;
        float mcx = (gp[0] + gp[2]) * 0.5f, mcy = (gp[1] + gp[3]) * 0.5f;
        float mw = gp[2] - gp[0], mh = gp[3] - gp[1];
        float t0 = (mcx - acx) / (aw * 0.1f);
        float t1 = (mcy - acy) / (ah * 0.1f);
        float t2 = logf(mw / aw + 1e-10f) / 0.2f;
        float t3 = logf(mh / ah + 1e-10f) / 0.2f;
        float4 pv = reinterpret_cast<const float4*>(pred)[ia];
        const float BETA = (float)(1.0 / 9.0);
        float d;
        d = fabsf(pv.x - t0); loc_acc += (d < BETA) ? 0.5f * d * d / BETA : d - 0.5f * BETA;
        d = fabsf(pv.y - t1); loc_acc += (d < BETA) ? 0.5f * d * d / BETA : d - 0.5f * BETA;
        d = fabsf(pv.z - t2); loc_acc += (d < BETA) ? 0.5f * d * d / BETA : d - 0.5f * BETA;
        d = fabsf(pv.w - t3); loc_acc += (d < BETA) ? 0.5f * d * d / BETA : d - 0.5f * BETA;
        // warp-aggregated per-batch positive count
        unsigned mm = __match_any_sync(__activemask(), b);
        if (lane == (__ffs(mm) - 1)) atomicAdd(&g_pos_cnt[b], __popc(mm));
        any = true;
    }
    unsigned ball = __ballot_sync(FULL, any);
    #pragma unroll
    for (int off = 16; off; off >>= 1) {
        ce_acc  += __shfl_xor_sync(FULL, ce_acc, off);
        loc_acc += __shfl_xor_sync(FULL, loc_acc, off);
    }
    if (lane == 0 && ball) {
        atomicAdd(&g_pos_ce, (double)ce_acc);
        atomicAdd(&g_loc_sum, (double)loc_acc);
    }
}

// -- K5: per-batch radix-select + top-K sum + fused finalize (last block)
__global__ void k5_select_sum(float* __restrict__ out) {
    __shared__ int hist[2048];
    __shared__ unsigned s_pref;
    __shared__ int s_rem, s_selbin, s_above;
    __shared__ double sred[32];
    int b = blockIdx.x;
    int tid = threadIdx.x;
    int lane = tid & 31;
    const float* base = g_mining + (size_t)b * NA;
    int K = 3 * g_pos_cnt[b];
    if (K > NA) K = NA;
    if (K > 0) {
        if (tid == 0) { s_rem = K; s_pref = 0u; }
        __syncthreads();
        for (int pass = 0; pass < 3; ++pass) {
            for (int i = tid; i < 2048; i += blockDim.x) hist[i] = 0;
            __syncthreads();
            unsigned pref = s_pref;
            int nb = (pass == 2) ? 1024 : 2048;
            for (int i0 = tid; i0 < NA; i0 += 4096) {
                unsigned u[4]; bool val[4];
                #pragma unroll
                for (int j = 0; j < 4; ++j) {
                    int i = i0 + j * 1024;
                    val[j] = (i < NA);
                    u[j] = val[j] ? fmap(base[i]) : 0u;
                }
                #pragma unroll
                for (int j = 0; j < 4; ++j) {
                    unsigned bin; bool ok = val[j];
                    if (pass == 0)      { bin = u[j] >> 21; }
                    else if (pass == 1) { ok = ok && ((u[j] >> 21) == pref);  bin = (u[j] >> 10) & 0x7FFu; }
                    else                { ok = ok && ((u[j] >> 10) == pref);  bin = u[j] & 0x3FFu; }
                    unsigned mm = __match_any_sync(FULL, ok ? bin : 0xFFFFFFFFu);
                    if (ok && lane == (__ffs(mm) - 1)) atomicAdd(&hist[bin], __popc(mm));
                }
            }
            __syncthreads();
            if (tid < 32) {
                int cs = nb >> 5;
                int s = 0;
                for (int k = 0; k < cs; k++) s += hist[lane * cs + k];
                int inc = s;
                #pragma unroll
                for (int off = 1; off < 32; off <<= 1) {
                    int t = __shfl_down_sync(FULL, inc, off);
                    if (lane + off < 32) inc += t;
                }
                int exc = inc - s;             // count in chunks strictly above
                int remv = s_rem;
                bool hit = (exc < remv) && (inc >= remv);
                unsigned bal = __ballot_sync(FULL, hit);
                int src = __ffs(bal) - 1;
                if (lane == src) {
                    int cum = exc, selbin = lane * cs;
                    for (int bb = lane * cs + cs - 1; bb >= lane * cs; --bb) {
                        int h = hist[bb];
                        if (cum + h >= remv) { selbin = bb; break; }
                        cum += h;
                    }
                    s_selbin = selbin;
                    s_above = cum;
                }
            }
            __syncthreads();
            if (tid == 0) {
                s_rem -= s_above;
                s_pref = (pass == 0) ? (unsigned)s_selbin
                                     : ((s_pref << ((pass == 2) ? 10 : 11)) | (unsigned)s_selbin);
            }
            __syncthreads();
        }
        // sum all values strictly above threshold (unrolled), plus tie term
        unsigned ut = s_pref;
        double s = 0.0;
        for (int i0 = tid; i0 < NA; i0 += 4096) {
            #pragma unroll
            for (int j = 0; j < 4; ++j) {
                int i = i0 + j * 1024;
                if (i < NA) {
                    float v = base[i];
                    if (fmap(v) > ut) s += (double)v;
                }
            }
        }
        #pragma unroll
        for (int off = 16; off; off >>= 1) s += __shfl_xor_sync(FULL, s, off);
        if (lane == 0) sred[tid >> 5] = s;
        __syncthreads();
        if (tid < 32) {
            double v = (tid < (int)(blockDim.x >> 5)) ? sred[tid] : 0.0;
            #pragma unroll
            for (int off = 16; off; off >>= 1) v += __shfl_xor_sync(FULL, v, off);
            if (tid == 0) {
                float tv = funmap(ut);
                if (isfinite(tv)) v += (double)s_rem * (double)tv;  // ties at threshold
                g_neg_sum[b] = v;
            }
        }
    } else if (tid == 0) {
        g_neg_sum[b] = 0.0;
    }
    // fused finalize: last block to finish writes the two outputs
    if (tid == 0) {
        __threadfence();
        int d = atomicAdd(&g_done, 1);
        if (d == NB - 1) {
            __threadfence();
            int np = 0; double ns = 0.0;
            for (int bb = 0; bb < NB; bb++) { np += g_pos_cnt[bb]; ns += g_neg_sum[bb]; }
            float npf = fmaxf(1.f, (float)np);
            double denom = (double)npf * 4.0;
            out[0] = (float)(g_loc_sum / denom);          // localisation_loss
            out[1] = (float)((g_pos_ce + ns) / denom);    // classification_loss
        }
    }
}

extern "C" void kernel_launch(void* const* d_in, const int* in_sizes, int n_in,
                              void* d_out, int out_size) {
    const float* conf    = (const float*)d_in[0];
    const float* pred    = (const float*)d_in[1];
    const float* gts     = (const float*)d_in[2];
    const int*   counts  = (const int*)d_in[3];
    const float* anchors = (const float*)d_in[4];
    float* out = (float*)d_out;

    k1_lse<<<dim3(NA / 8, NB), 256>>>(conf);
    k2a_match<<<dim3((NA + 255) / 256, NB), 256>>>(gts, counts, anchors);
    k2b3_reduce_scatter<<<NB, 512>>>(counts);
    k4_pos<<<1024, 256>>>(conf, pred, gts, anchors);
    k5_select_sum<<<NB, 1024>>>(out);
}

// round 12
// speedup vs baseline: 1.8545x; 1.2879x over previous
#include <cuda_runtime.h>
#include <math.h>

#define NB 16
#define NA 65472
#define NC 81
#define NG 50
#define POS_TH 0.5f
#define FULL 0xffffffffu
#define NBLK 256                 // k2a blocks per batch
#define BMW (NA / 32)            // bitmap words per batch = 2046

__device__ float g_mining[NB * NA];
__device__ unsigned long long g_part[NB * NG * NBLK];
__device__ unsigned g_bm[NB * BMW];          // forced-anchor bitmap
__device__ unsigned g_plist[NB * NA + 1024];
__device__ int    g_plist_cnt;
__device__ double g_pos_ce;
__device__ double g_loc_sum;
__device__ int    g_pos_cnt[NB];
__device__ double g_neg_sum[NB];
__device__ int    g_done;

__device__ __forceinline__ unsigned fmap(float v) {
    unsigned u = __float_as_uint(v);
    return (u & 0x80000000u) ? ~u : (u | 0x80000000u);
}
__device__ __forceinline__ float funmap(unsigned u) {
    unsigned b = (u & 0x80000000u) ? (u & 0x7FFFFFFFu) : ~u;
    return __uint_as_float(b);
}

// ----- K1: logsumexp -> mining (2 anchors per warp) + init + bitmap zero
__global__ void k1_lse(const float* __restrict__ conf) {
    if (blockIdx.y == 0 && blockIdx.x < 32) {
        int gid = blockIdx.x * 256 + threadIdx.x;
        if (gid == 0) { g_pos_ce = 0.0; g_loc_sum = 0.0; g_plist_cnt = 0; g_done = 0; }
        if (gid < NB) { g_pos_cnt[gid] = 0; g_neg_sum[gid] = 0.0; }
        for (int i = gid; i < NB * BMW; i += 32 * 256) g_bm[i] = 0u;
    }
    int warp = threadIdx.x >> 5;
    int lane = threadIdx.x & 31;
    int a0 = (blockIdx.x * 8 + warp) * 2;          // 16 anchors per block
    int b = blockIdx.y;
    const float* p0 = conf + ((size_t)b * NA + a0) * NC;
    const float* p1 = p0 + NC;
    float a_x0 = p0[lane];
    float b_x0 = p1[lane];
    float a_x1 = p0[32 + lane];
    float b_x1 = p1[32 + lane];
    float sa = __expf(a_x0) + __expf(a_x1);
    float sb = __expf(b_x0) + __expf(b_x1);
    if (lane < NC - 64) {
        sa += __expf(p0[64 + lane]);
        sb += __expf(p1[64 + lane]);
    }
    #pragma unroll
    for (int off = 16; off; off >>= 1) {
        sa += __shfl_xor_sync(FULL, sa, off);
        sb += __shfl_xor_sync(FULL, sb, off);
    }
    if (lane == 0) {
        g_mining[(size_t)b * NA + a0]     = __logf(sa) - a_x0;   // lse - conf[...,0]
        g_mining[(size_t)b * NA + a0 + 1] = __logf(sb) - b_x0;
    }
}

// --- K2a: per-anchor best + smem per-(warp,g) partials -> per-(block,g)
__global__ void k2a_match(const float* __restrict__ gts, const int* __restrict__ counts,
                          const float* __restrict__ anchors) {
    __shared__ float4 sbox[NG];
    __shared__ float  sarea[NG];
    __shared__ unsigned long long spart[8][NG];
    int b = blockIdx.y;
    int tid = threadIdx.x;
    int a = blockIdx.x * blockDim.x + tid;
    int lane = tid & 31;
    int wid = tid >> 5;
    if (tid < NG) {
        const float* gp = gts + ((size_t)b * NG + tid) * 5;
        float4 bx = make_float4(gp[0], gp[1], gp[2], gp[3]);
        sbox[tid] = bx;
        sarea[tid] = (bx.z - bx.x) * (bx.w - bx.y);
    }
    __syncthreads();
    int count = counts[b];
    float4 v = make_float4(0.f, 0.f, 0.f, 0.f);
    if (a < NA) v = reinterpret_cast<const float4*>(anchors)[a];
    float areaA = (v.z - v.x) * (v.w - v.y);
    float bi = -1.f;
    int bidx = 0;
    for (int g = 0; g < count; ++g) {
        float4 bx = sbox[g];
        float wx = fminf(v.z, bx.z) - fmaxf(v.x, bx.x);
        float wy = fminf(v.w, bx.w) - fmaxf(v.y, bx.y);
        wx = fmaxf(wx, 0.f); wy = fmaxf(wy, 0.f);
        float inter = wx * wy;
        float iou = __fdividef(inter, areaA + sarea[g] - inter + 1e-10f);
        if (a >= NA) iou = 0.f;
        if (iou > bi) { bi = iou; bidx = g; }          // first max kept (strict >)
        // per-(warp,g) argmax partial (iou >= 0 so uint order = float order)
        unsigned iu = __float_as_uint(iou);
        unsigned mu = __reduce_max_sync(FULL, iu);
        unsigned ball = __ballot_sync(FULL, iu == mu);
        if (lane == (__ffs(ball) - 1)) {               // lowest lane = smallest anchor
            spart[wid][g] = ((unsigned long long)mu << 32) | (unsigned)(~(unsigned)a);
        }
    }
    bool reg_pos = (a < NA) && (bi >= POS_TH);
    // warp-aggregated append of regular positives (b|a|g packed)
    unsigned pball = __ballot_sync(FULL, reg_pos);
    if (pball) {
        int leader = __ffs(pball) - 1;
        int base = 0;
        if (lane == leader) base = atomicAdd(&g_plist_cnt, __popc(pball));
        base = __shfl_sync(FULL, base, leader);
        if (reg_pos) {
            int off = __popc(pball & ((1u << lane) - 1u));
            g_plist[base + off] = ((unsigned)b << 23) | ((unsigned)a << 6) | (unsigned)bidx;
        }
    }
    __syncthreads();
    // reduce 8 warp partials per g -> one per block
    if (tid < count) {
        unsigned long long best = spart[0][tid];
        #pragma unroll
        for (int k = 1; k < 8; ++k) {
            unsigned long long vv = spart[k][tid];
            if (vv > best) best = vv;
        }
        g_part[((size_t)b * NG + tid) * NBLK + blockIdx.x] = best;
    }
}

// --- K2b3: reduce per-block partials -> best anchor per g; dedup + append
__global__ void k2b3_reduce_scatter(const int* __restrict__ counts) {
    __shared__ int s_anch[NG];
    int b = blockIdx.x;
    int tid = threadIdx.x;
    int lane = tid & 31;
    int wid = tid >> 5;                 // 16 warps
    int count = counts[b];
    for (int g = wid; g < count; g += 16) {
        const unsigned long long* pp = g_part + ((size_t)b * NG + g) * NBLK;
        unsigned long long best = 0ull;
        #pragma unroll
        for (int k = 0; k < NBLK / 32; ++k) {
            unsigned long long vv = pp[lane + 32 * k];
            if (vv > best) best = vv;
        }
        #pragma unroll
        for (int off = 16; off; off >>= 1) {
            unsigned long long o = __shfl_xor_sync(FULL, best, off);
            if (o > best) best = o;
        }
        if (lane == 0) s_anch[g] = (int)(~(unsigned)(best & 0xFFFFFFFFu));
    }
    __syncthreads();
    // dedup (last write wins) + bitmap + append forced positives
    if (tid < count) {
        int g = tid;
        int a = s_anch[g];
        bool skip = false;
        for (int g2 = g + 1; g2 < count; ++g2)
            if (s_anch[g2] == a) { skip = true; break; }
        if (!skip) {
            atomicOr(&g_bm[b * BMW + (a >> 5)], 1u << (a & 31));
            int idx = atomicAdd(&g_plist_cnt, 1);
            g_plist[idx] = (1u << 27) | ((unsigned)b << 23) | ((unsigned)a << 6) | (unsigned)g;
        }
    }
}

// ------- K4: compact positives: CE, SmoothL1, counts, mask mining = -inf
__global__ void k4_pos(const float* __restrict__ conf, const float* __restrict__ pred,
                       const float* __restrict__ gts, const float* __restrict__ anchors) {
    int n = g_plist_cnt;
    int lane = threadIdx.x & 31;
    float ce_acc = 0.f, loc_acc = 0.f;
    for (int i = blockIdx.x * blockDim.x + threadIdx.x; i < n; i += gridDim.x * blockDim.x) {
        unsigned e = g_plist[i];
        int b = (e >> 23) & 15;
        int a = (e >> 6) & 0x1FFFF;
        int g = e & 63;
        bool forced = (e >> 27) & 1;
        if (!forced) {
            // anchor was later force-matched: its entry is superseded
            if ((g_bm[b * BMW + (a >> 5)] >> (a & 31)) & 1) continue;
        }
        size_t ia = (size_t)b * NA + a;
        const float* gp = gts + ((size_t)b * NG + g) * 5;
        int label = (int)gp[4];
        const float* cp = conf + ia * NC;
        float m = g_mining[ia];
        ce_acc += m + cp[0] - cp[label];              // lse - conf[label]
        g_mining[ia] = -INFINITY;
        float4 av = reinterpret_cast<const float4*>(anchors)[a];
        float acx = (av.x + av.z) * 0.5f, acy = (av.y + av.w) * 0.5f;
        float aw = av.z - av.x, ah = av.w - av.y;
        float mcx = (gp[0] + gp[2]) * 0.5f, mcy = (gp[1] + gp[3]) * 0.5f;
        float mw = gp[2] - gp[0], mh = gp[3] - gp[1];
        float t0 = (mcx - acx) / (aw * 0.1f);
        float t1 = (mcy - acy) / (ah * 0.1f);
        float t2 = logf(mw / aw + 1e-10f) / 0.2f;
        float t3 = logf(mh / ah + 1e-10f) / 0.2f;
        float4 pv = reinterpret_cast<const float4*>(pred)[ia];
        const float BETA = (float)(1.0 / 9.0);
        float d;
        d = fabsf(pv.x - t0); loc_acc += (d < BETA) ? 0.5f * d * d / BETA : d - 0.5f * BETA;
        d = fabsf(pv.y - t1); loc_acc += (d < BETA) ? 0.5f * d * d / BETA : d - 0.5f * BETA;
        d = fabsf(pv.z - t2); loc_acc += (d < BETA) ? 0.5f * d * d / BETA : d - 0.5f * BETA;
        d = fabsf(pv.w - t3); loc_acc += (d < BETA) ? 0.5f * d * d / BETA : d - 0.5f * BETA;
        // warp-aggregated per-batch positive count
        unsigned mm = __match_any_sync(__activemask(), b);
        if ((__ffs(mm) - 1) == lane) atomicAdd(&g_pos_cnt[b], __popc(mm));
    }
    #pragma unroll
    for (int off = 16; off; off >>= 1) {
        ce_acc  += __shfl_xor_sync(FULL, ce_acc, off);
        loc_acc += __shfl_xor_sync(FULL, loc_acc, off);
    }
    if (lane == 0 && (ce_acc != 0.f || loc_acc != 0.f)) {
        atomicAdd(&g_pos_ce, (double)ce_acc);
        atomicAdd(&g_loc_sum, (double)loc_acc);
    }
}

// -- K5: per-batch radix-select + top-K sum + fused finalize (last block)
__global__ void k5_select_sum(float* __restrict__ out) {
    __shared__ int hist[2048];
    __shared__ unsigned s_pref;
    __shared__ int s_rem, s_selbin, s_above;
    __shared__ double sred[32];
    int b = blockIdx.x;
    int tid = threadIdx.x;
    int lane = tid & 31;
    const float* base = g_mining + (size_t)b * NA;
    int K = 3 * g_pos_cnt[b];
    if (K > NA) K = NA;
    if (K > 0) {
        if (tid == 0) { s_rem = K; s_pref = 0u; }
        __syncthreads();
        for (int pass = 0; pass < 3; ++pass) {
            for (int i = tid; i < 2048; i += blockDim.x) hist[i] = 0;
            __syncthreads();
            unsigned pref = s_pref;
            int nb = (pass == 2) ? 1024 : 2048;
            for (int i0 = tid; i0 < NA; i0 += 8192) {
                unsigned u[8]; bool val[8];
                #pragma unroll
                for (int j = 0; j < 8; ++j) {
                    int i = i0 + j * 1024;
                    val[j] = (i < NA);
                    u[j] = val[j] ? fmap(base[i]) : 0u;
                }
                #pragma unroll
                for (int j = 0; j < 8; ++j) {
                    unsigned bin; bool ok = val[j];
                    if (pass == 0)      { bin = u[j] >> 21; }
                    else if (pass == 1) { ok = ok && ((u[j] >> 21) == pref);  bin = (u[j] >> 10) & 0x7FFu; }
                    else                { ok = ok && ((u[j] >> 10) == pref);  bin = u[j] & 0x3FFu; }
                    unsigned mm = __match_any_sync(FULL, ok ? bin : 0xFFFFFFFFu);
                    if (ok && lane == (__ffs(mm) - 1)) atomicAdd(&hist[bin], __popc(mm));
                }
            }
            __syncthreads();
            if (tid < 32) {
                int cs = nb >> 5;
                int s = 0;
                for (int k = 0; k < cs; k++) s += hist[lane * cs + k];
                int inc = s;
                #pragma unroll
                for (int off = 1; off < 32; off <<= 1) {
                    int t = __shfl_down_sync(FULL, inc, off);
                    if (lane + off < 32) inc += t;
                }
                int exc = inc - s;             // count in chunks strictly above
                int remv = s_rem;
                bool hit = (exc < remv) && (inc >= remv);
                unsigned bal = __ballot_sync(FULL, hit);
                int src = __ffs(bal) - 1;
                if (lane == src) {
                    int cum = exc, selbin = lane * cs;
                    for (int bb = lane * cs + cs - 1; bb >= lane * cs; --bb) {
                        int h = hist[bb];
                        if (cum + h >= remv) { selbin = bb; break; }
                        cum += h;
                    }
                    s_selbin = selbin;
                    s_above = cum;
                }
            }
            __syncthreads();
            if (tid == 0) {
                s_rem -= s_above;
                s_pref = (pass == 0) ? (unsigned)s_selbin
                                     : ((s_pref << ((pass == 2) ? 10 : 11)) | (unsigned)s_selbin);
            }
            __syncthreads();
        }
        // sum all values strictly above threshold (unrolled x8), plus tie term
        unsigned ut = s_pref;
        double s = 0.0;
        for (int i0 = tid; i0 < NA; i0 += 8192) {
            #pragma unroll
            for (int j = 0; j < 8; ++j) {
                int i = i0 + j * 1024;
                if (i < NA) {
                    float vv = base[i];
                    if (fmap(vv) > ut) s += (double)vv;
                }
            }
        }
        #pragma unroll
        for (int off = 16; off; off >>= 1) s += __shfl_xor_sync(FULL, s, off);
        if (lane == 0) sred[tid >> 5] = s;
        __syncthreads();
        if (tid < 32) {
            double vv = (tid < (int)(blockDim.x >> 5)) ? sred[tid] : 0.0;
            #pragma unroll
            for (int off = 16; off; off >>= 1) vv += __shfl_xor_sync(FULL, vv, off);
            if (tid == 0) {
                float tv = funmap(ut);
                if (isfinite(tv)) vv += (double)s_rem * (double)tv;  // ties at threshold
                g_neg_sum[b] = vv;
            }
        }
    } else if (tid == 0) {
        g_neg_sum[b] = 0.0;
    }
    // fused finalize: last block to finish writes the two outputs
    if (tid == 0) {
        __threadfence();
        int d = atomicAdd(&g_done, 1);
        if (d == NB - 1) {
            __threadfence();
            int np = 0; double ns = 0.0;
            for (int bb = 0; bb < NB; bb++) { np += g_pos_cnt[bb]; ns += g_neg_sum[bb]; }
            float npf = fmaxf(1.f, (float)np);
            double denom = (double)npf * 4.0;
            out[0] = (float)(g_loc_sum / denom);          // localisation_loss
            out[1] = (float)((g_pos_ce + ns) / denom);    // classification_loss
        }
    }
}

extern "C" void kernel_launch(void* const* d_in, const int* in_sizes, int n_in,
                              void* d_out, int out_size) {
    const float* conf    = (const float*)d_in[0];
    const float* pred    = (const float*)d_in[1];
    const float* gts     = (const float*)d_in[2];
    const int*   counts  = (const int*)d_in[3];
    const float* anchors = (const float*)d_in[4];
    float* out = (float*)d_out;

    k1_lse<<<dim3(NA / 16, NB), 256>>>(conf);
    k2a_match<<<dim3(NBLK, NB), 256>>>(gts, counts, anchors);
    k2b3_reduce_scatter<<<NB, 512>>>(counts);
    k4_pos<<<1024, 256>>>(conf, pred, gts, anchors);
    k5_select_sum<<<NB, 1024>>>(out);
}